// round 7
// baseline (speedup 1.0000x reference)
#include <cuda_runtime.h>
#include <cuda_bf16.h>
#include <math.h>
#include <stdint.h>

#define LL 1024
#define BB 128
#define DD 256
#define HH 256

#define XN (LL * BB * DD)     // 33554432 X elements
#define WN (HH * DD)          // 65536 Wx elements

// Pre-split bf16 scratch (static device arrays — allowed)
__device__ __align__(16) __nv_bfloat16 g_xhi[XN];
__device__ __align__(16) __nv_bfloat16 g_xlo[XN];
__device__ __align__(16) __nv_bfloat16 g_whi[WN];
__device__ __align__(16) __nv_bfloat16 g_wlo[WN];

__device__ __forceinline__ uint32_t smem_u32(const void* p) {
    uint32_t a;
    asm("{ .reg .u64 t; cvta.to.shared.u64 t, %1; cvt.u32.u64 %0, t; }"
        : "=r"(a) : "l"(p));
    return a;
}

__device__ __forceinline__ void split2(float a, float b, uint32_t& h, uint32_t& l) {
    __nv_bfloat16 ha = __float2bfloat16(a);
    __nv_bfloat16 hb = __float2bfloat16(b);
    float ra = a - __bfloat162float(ha);
    float rb = b - __bfloat162float(hb);
    __nv_bfloat16 la = __float2bfloat16(ra);
    __nv_bfloat16 lb = __float2bfloat16(rb);
    h = (uint32_t)reinterpret_cast<unsigned short&>(ha) |
        ((uint32_t)reinterpret_cast<unsigned short&>(hb) << 16);
    l = (uint32_t)reinterpret_cast<unsigned short&>(la) |
        ((uint32_t)reinterpret_cast<unsigned short&>(lb) << 16);
}

// ====================================================================
// Kernel 0: one-shot fp32 -> split-bf16 (hi, lo) for X and Wx.
// ====================================================================
#define CV_JOBS ((XN + WN) / 4)

__global__ __launch_bounds__(256) void convert_kernel(
    const float* __restrict__ X, const float* __restrict__ Wx)
{
    int i = blockIdx.x * 256 + threadIdx.x;
    if (i >= CV_JOBS) return;
    float4 v;
    if (i < XN / 4) v = ((const float4*)X)[i];
    else            v = ((const float4*)Wx)[i - XN / 4];
    uint2 hi, lo;
    split2(v.x, v.y, hi.x, lo.x);
    split2(v.z, v.w, hi.y, lo.y);
    if (i < XN / 4) {
        *(uint2*)(g_xhi + (size_t)i * 4) = hi;
        *(uint2*)(g_xlo + (size_t)i * 4) = lo;
    } else {
        size_t o = (size_t)(i - XN / 4) * 4;
        *(uint2*)(g_whi + o) = hi;
        *(uint2*)(g_wlo + o) = lo;
    }
}

// ====================================================================
// Kernel 1: xproj GEMM via mma.sync bf16 split-3, fp32 accum.
// ====================================================================
#define XP_STRIDE_B 144
#define XP_TILE_B   (128 * XP_STRIDE_B)
#define XP_AHI 0
#define XP_ALO XP_TILE_B
#define XP_WHI (2 * XP_TILE_B)
#define XP_WLO (3 * XP_TILE_B)
#define XP_SMEM (4 * XP_TILE_B)

__device__ __forceinline__ void ldm_x4(uint32_t& r0, uint32_t& r1,
                                       uint32_t& r2, uint32_t& r3, uint32_t addr) {
    asm volatile("ldmatrix.sync.aligned.m8n8.x4.shared.b16 {%0,%1,%2,%3}, [%4];"
                 : "=r"(r0), "=r"(r1), "=r"(r2), "=r"(r3) : "r"(addr));
}

__device__ __forceinline__ void mma16816(float* c, const uint32_t* a,
                                         uint32_t b0, uint32_t b1) {
    asm volatile(
        "mma.sync.aligned.m16n8k16.row.col.f32.bf16.bf16.f32 "
        "{%0,%1,%2,%3}, {%4,%5,%6,%7}, {%8,%9}, {%0,%1,%2,%3};"
        : "+f"(c[0]), "+f"(c[1]), "+f"(c[2]), "+f"(c[3])
        : "r"(a[0]), "r"(a[1]), "r"(a[2]), "r"(a[3]), "r"(b0), "r"(b1));
}

__global__ __launch_bounds__(256) void xproj_mma_kernel(
    const float* __restrict__ bx,
    float* __restrict__ C)
{
    extern __shared__ char smem[];
    const uint32_t sb = smem_u32(smem);
    const int tid = threadIdx.x;
    const int wid = tid >> 5;
    const int l   = tid & 31;
    const int warp_m = wid & 3;
    const int warp_n = wid >> 2;
    const int m0 = blockIdx.x * 128;
    const int n0 = blockIdx.y * 128;

    float acc[2][8][4];
#pragma unroll
    for (int t = 0; t < 2; t++)
#pragma unroll
        for (int nb = 0; nb < 8; nb++)
#pragma unroll
            for (int i = 0; i < 4; i++) acc[t][nb][i] = 0.0f;

    const uint32_t aRowOff = (uint32_t)((warp_m * 32 + (l & 15)) * XP_STRIDE_B +
                                        (l >> 4) * 16);
    const uint32_t bRowOff = (uint32_t)((warp_n * 64 + ((l >> 4) << 3) + (l & 7)) * XP_STRIDE_B +
                                        ((l >> 3) & 1) * 16);

    for (int c = 0; c < 4; ++c) {
        const int k0 = c * 64;
#pragma unroll
        for (int q = 0; q < 4; ++q) {
            int job = q * 256 + tid;
            int row = job >> 3, kg = job & 7;
            size_t src = (size_t)(m0 + row) * DD + k0 + kg * 8;
            int off = row * XP_STRIDE_B + kg * 16;
            *(uint4*)(smem + XP_AHI + off) = *(const uint4*)(g_xhi + src);
            *(uint4*)(smem + XP_ALO + off) = *(const uint4*)(g_xlo + src);
        }
#pragma unroll
        for (int q = 0; q < 4; ++q) {
            int job = q * 256 + tid;
            int row = job >> 3, kg = job & 7;
            size_t src = (size_t)(n0 + row) * DD + k0 + kg * 8;
            int off = row * XP_STRIDE_B + kg * 16;
            *(uint4*)(smem + XP_WHI + off) = *(const uint4*)(g_whi + src);
            *(uint4*)(smem + XP_WLO + off) = *(const uint4*)(g_wlo + src);
        }
        __syncthreads();

#pragma unroll
        for (int ks = 0; ks < 4; ++ks) {
            const uint32_t kOff = (uint32_t)(ks * 32);
            uint32_t ahi[2][4], alo[2][4];
#pragma unroll
            for (int t = 0; t < 2; t++) {
                uint32_t abase = aRowOff + (uint32_t)(t * 16 * XP_STRIDE_B) + kOff;
                ldm_x4(ahi[t][0], ahi[t][1], ahi[t][2], ahi[t][3], sb + XP_AHI + abase);
                ldm_x4(alo[t][0], alo[t][1], alo[t][2], alo[t][3], sb + XP_ALO + abase);
            }
#pragma unroll
            for (int g = 0; g < 4; ++g) {
                uint32_t bbase = bRowOff + (uint32_t)(g * 16 * XP_STRIDE_B) + kOff;
                uint32_t h0, h1, h2, h3, q0, q1, q2, q3;
                ldm_x4(h0, h1, h2, h3, sb + XP_WHI + bbase);
                ldm_x4(q0, q1, q2, q3, sb + XP_WLO + bbase);
#pragma unroll
                for (int t = 0; t < 2; t++) {
                    mma16816(acc[t][2 * g],     ahi[t], h0, h1);
                    mma16816(acc[t][2 * g + 1], ahi[t], h2, h3);
                    mma16816(acc[t][2 * g],     alo[t], h0, h1);
                    mma16816(acc[t][2 * g + 1], alo[t], h2, h3);
                    mma16816(acc[t][2 * g],     ahi[t], q0, q1);
                    mma16816(acc[t][2 * g + 1], ahi[t], q2, q3);
                }
            }
        }
        __syncthreads();
    }

    const int mrow = m0 + warp_m * 32 + (l >> 2);
    const int ncol = n0 + warp_n * 64 + 2 * (l & 3);
#pragma unroll
    for (int t = 0; t < 2; t++) {
#pragma unroll
        for (int nb = 0; nb < 8; nb++) {
            int nn = ncol + nb * 8;
            float2 bv = *(const float2*)(bx + nn);
            int r0 = mrow + t * 16;
            float2 o0 = make_float2(acc[t][nb][0] + bv.x, acc[t][nb][1] + bv.y);
            float2 o1 = make_float2(acc[t][nb][2] + bv.x, acc[t][nb][3] + bv.y);
            *(float2*)(C + (size_t)r0 * HH + nn) = o0;
            *(float2*)(C + (size_t)(r0 + 8) * HH + nn) = o1;
        }
    }
}

// ====================================================================
// Kernel 2: persistent scan v2.
//  - xp prefetched one step ahead (hides DRAM latency)
//  - balanced finalize: half0 finalizes j<128, half1 finalizes j>=128
//  - 8 accumulators, bh in register
// ====================================================================
__global__ __launch_bounds__(512, 1) void scan_kernel(
    const float* __restrict__ h0,
    const float* __restrict__ Wh,
    const float* __restrict__ bh,
    float* __restrict__ out,
    int hasFinal)
{
    extern __shared__ float smemf[];
    float4* Ws4  = (float4*)smemf;           // 16*256 float4 = 64 KB
    float*  hbuf = smemf + 16 * 256 * 4;     // 512 (ping-pong)
    float*  part = hbuf + 512;               // 256

    const int tid  = threadIdx.x;
    const int j    = tid & 255;
    const int half = tid >> 8;
    const int b    = blockIdx.x;
    const int kb   = half * 128;
    const bool isFin = half ? (j >= 128) : (j < 128);

    // register-resident weights: k in [kb, kb+96)
    float4 wr[24];
    const float4* wrow = (const float4*)(Wh + (size_t)j * HH + kb);
#pragma unroll
    for (int i = 0; i < 24; i++) wr[i] = wrow[i];

    // shared weights: g<8 -> k = 96+4g (half 0), g>=8 -> k = 224+4(g-8) (half 1)
    for (int idx = tid; idx < 16 * 256; idx += 512) {
        int g  = idx >> 8;
        int jj = idx & 255;
        int kk = (g < 8) ? (96 + 4 * g) : (224 + 4 * (g - 8));
        Ws4[g * 256 + jj] = *(const float4*)(Wh + (size_t)jj * HH + kk);
    }
    if (tid < 256) hbuf[tid] = h0[(size_t)b * HH + tid];

    const float bh_r = bh[j];
    float* const outp = out + (size_t)b * HH + j;   // step stride BB*HH

    // prefetch xp for t=0
    float xp_next = 0.0f;
    if (isFin) xp_next = outp[0];
    __syncthreads();

    int cur = 0;
    for (int t = 0; t < LL; ++t) {
        const float xp = xp_next;
        // prefetch next step's xp (independent of everything this step)
        if (isFin && t + 1 < LL) xp_next = outp[(size_t)(t + 1) * (BB * HH)];

        const float4* h4 = (const float4*)(hbuf + cur * 256 + kb);
        float a0 = 0.f, a1 = 0.f, a2 = 0.f, a3 = 0.f;
        float a4 = 0.f, a5 = 0.f, a6 = 0.f, a7 = 0.f;
#pragma unroll
        for (int i = 0; i < 24; i += 2) {
            float4 hv0 = h4[i];
            float4 hv1 = h4[i + 1];
            a0 = fmaf(wr[i].x, hv0.x, a0);
            a1 = fmaf(wr[i].y, hv0.y, a1);
            a2 = fmaf(wr[i].z, hv0.z, a2);
            a3 = fmaf(wr[i].w, hv0.w, a3);
            a4 = fmaf(wr[i + 1].x, hv1.x, a4);
            a5 = fmaf(wr[i + 1].y, hv1.y, a5);
            a6 = fmaf(wr[i + 1].z, hv1.z, a6);
            a7 = fmaf(wr[i + 1].w, hv1.w, a7);
        }
        const float4* wsp = Ws4 + half * 8 * 256 + j;
#pragma unroll
        for (int g = 0; g < 8; g += 2) {
            float4 wv0 = wsp[g * 256];
            float4 wv1 = wsp[(g + 1) * 256];
            float4 hv0 = h4[24 + g];
            float4 hv1 = h4[24 + g + 1];
            a0 = fmaf(wv0.x, hv0.x, a0);
            a1 = fmaf(wv0.y, hv0.y, a1);
            a2 = fmaf(wv0.z, hv0.z, a2);
            a3 = fmaf(wv0.w, hv0.w, a3);
            a4 = fmaf(wv1.x, hv1.x, a4);
            a5 = fmaf(wv1.y, hv1.y, a5);
            a6 = fmaf(wv1.z, hv1.z, a6);
            a7 = fmaf(wv1.w, hv1.w, a7);
        }
        float acc = ((a0 + a1) + (a2 + a3)) + ((a4 + a5) + (a6 + a7));

        if (!isFin) part[j] = acc;
        __syncthreads();

        if (isFin) {
            float v  = acc + part[j] + xp + bh_r;
            float hn = tanhf(v);
            hbuf[(cur ^ 1) * 256 + j] = hn;
            outp[(size_t)t * (BB * HH)] = hn;
            if (hasFinal && t == LL - 1)
                outp[(size_t)LL * (BB * HH)] = hn;
        }
        __syncthreads();
        cur ^= 1;
    }
}

// ====================================================================
// launch
// ====================================================================
extern "C" void kernel_launch(void* const* d_in, const int* in_sizes, int n_in,
                              void* d_out, int out_size)
{
    const float* x   = (const float*)d_in[0];
    const float* h0  = (const float*)d_in[1];
    const float* Wxw = (const float*)d_in[2];
    const float* Wxb = (const float*)d_in[3];
    const float* Whw = (const float*)d_in[4];
    const float* Whb = (const float*)d_in[5];
    float* out = (float*)d_out;

    (void)in_sizes; (void)n_in;

    cudaFuncSetAttribute(xproj_mma_kernel, cudaFuncAttributeMaxDynamicSharedMemorySize, XP_SMEM);
    const int smemScan = (16 * 256 * 4 + 512 + 256) * (int)sizeof(float);
    cudaFuncSetAttribute(scan_kernel, cudaFuncAttributeMaxDynamicSharedMemorySize, smemScan);

    convert_kernel<<<(CV_JOBS + 255) / 256, 256>>>(x, Wxw);

    dim3 g1(LL * BB / 128, HH / 128);   // (1024, 2)
    xproj_mma_kernel<<<g1, 256, XP_SMEM>>>(Wxb, out);

    const int hasFinal = (out_size >= LL * BB * HH + BB * HH) ? 1 : 0;
    scan_kernel<<<BB, 512, smemScan>>>(h0, Whw, Whb, out, hasFinal);
}